// round 16
// baseline (speedup 1.0000x reference)
#include <cuda_runtime.h>
#include <cuda_fp16.h>
#include <cstdint>

// ---------------------------------------------------------------------------
// CNF Dopri5 solver, tensor-core GEMMs, fp16 2-pass weights (E single-pass).
// R15 = R14 (best, 930us) + depth-2 software pipeline on the LDSM B-fragment
// stream in all GEMM loops (weights were already double-buffered).
// 32 samples/CTA, 256 CTAs, 256 threads, 2 CTAs/SM.
// ---------------------------------------------------------------------------

#define DB 64
#define HB 256
#define BT 8192
#define NSTEPS 10
#define SB 32
#define NTHREADS 256
#define NBLOCKS (BT / SB)      // 256

#define LDH 264
#define LDY 72
#define LDF 68
#define LDK 68

typedef __half f16;

__device__ __align__(16) f16 g_W1hf[HB * DB], g_W1lf[HB * DB];     // KC=4
__device__ __align__(16) f16 g_W2hf[HB * HB], g_W2lf[HB * HB];     // KC=16
__device__ __align__(16) f16 g_Ehf [HB * HB];                      // KC=16 single
__device__ __align__(16) f16 g_W3hf[DB * HB], g_W3lf[DB * HB];     // KC=16

__constant__ float c_A[6][6] = {
    { 0.2f, 0.f, 0.f, 0.f, 0.f, 0.f },
    { 3.f/40.f, 9.f/40.f, 0.f, 0.f, 0.f, 0.f },
    { 44.f/45.f, -56.f/15.f, 32.f/9.f, 0.f, 0.f, 0.f },
    { 19372.f/6561.f, -25360.f/2187.f, 64448.f/6561.f, -212.f/729.f, 0.f, 0.f },
    { 9017.f/3168.f, -355.f/33.f, 46732.f/5247.f, 49.f/176.f, -5103.f/18656.f, 0.f },
    { 35.f/384.f, 0.f, 500.f/1113.f, 125.f/192.f, -2187.f/6784.f, 11.f/84.f }
};
__constant__ float c_CL[6] = {
    35.f/384.f, 0.f, 500.f/1113.f, 125.f/192.f, -2187.f/6784.f, 11.f/84.f
};

__device__ __forceinline__ void wsplit(float v, f16& hi, f16& lo) {
    hi = __float2half(v);
    lo = __float2half(v - __half2float(hi));
}

__device__ __forceinline__ int pidx(int m, int k, int KC) {
    int mtile = m >> 4;
    int kc    = k >> 4;
    int lane  = (m & 7) * 4 + ((k & 7) >> 1);
    int reg   = ((k >> 3) & 1) * 2 + ((m >> 3) & 1);
    int half_ = k & 1;
    return (((mtile * KC + kc) * 32 + lane) * 4 + reg) * 2 + half_;
}

// 2-MUFU activation: softplus + sigmoid from tanh.approx + log.
__device__ __forceinline__ void act(float z, float& sp, float& sg) {
    float u;
    asm("tanh.approx.f32 %0, %1;" : "=f"(u) : "f"(-0.5f * fabsf(z)));
    float q = 0.5f - 0.5f * u;             // sigmoid(|z|) in [0.5, 1)
    sp = fmaxf(z, 0.f) - __logf(q);        // softplus(z)
    sg = (z > 0.f) ? q : 1.f - q;          // sigmoid(z)
}

#define MMA16816(dd, a0, a1, a2, a3, bb0, bb1) \
    asm volatile("mma.sync.aligned.m16n8k16.row.col.f32.f16.f16.f32 " \
        "{%0,%1,%2,%3}, {%4,%5,%6,%7}, {%8,%9}, {%0,%1,%2,%3};" \
        : "+f"(dd[0]), "+f"(dd[1]), "+f"(dd[2]), "+f"(dd[3]) \
        : "r"(a0), "r"(a1), "r"(a2), "r"(a3), "r"(bb0), "r"(bb1))

#define LDSM4(rr0, rr1, rr2, rr3, saddr) \
    asm volatile("ldmatrix.sync.aligned.m8n8.x4.shared.b16 {%0,%1,%2,%3}, [%4];" \
        : "=r"(rr0), "=r"(rr1), "=r"(rr2), "=r"(rr3) : "r"(saddr))

// Fragment load from a hoisted pointer (strength-reduced addressing).
__device__ __forceinline__ void ldfp(const uint4* p, uint32_t a[4]) {
    uint4 v = *p;
    a[0] = v.x; a[1] = v.y; a[2] = v.z; a[3] = v.w;
}

// ---------------------------------------------------------------------------
__global__ void cnf_prep_kernel(const float* __restrict__ W1,
                                const float* __restrict__ W2,
                                const float* __restrict__ W3) {
    int i = blockIdx.x;
    int j = threadIdx.x;
    float g = 0.f;
    #pragma unroll
    for (int d = 0; d < DB; ++d)
        g += W1[i * DB + d] * W3[d * HB + j];
    g_Ehf[pidx(j, i, 16)] = __float2half(W2[j * HB + i] * g);
    {
        int q = pidx(i, j, 16);
        wsplit(W2[i * HB + j], g_W2hf[q], g_W2lf[q]);
    }
    if (j < DB) {
        int q = pidx(i, j, 4);
        wsplit(W1[i * DB + j], g_W1hf[q], g_W1lf[q]);
    }
    if (i < DB) {
        int q = pidx(i, j, 16);
        wsplit(W3[i * HB + j], g_W3hf[q], g_W3lf[q]);
    }
}

// ---------------------------------------------------------------------------
__global__ void __launch_bounds__(NTHREADS, 2)
cnf_main_kernel(const float* __restrict__ x,
                const float* __restrict__ ld0,
                const float* __restrict__ b1g,
                const float* __restrict__ b2g,
                const float* __restrict__ b3g,
                const float* __restrict__ Tptr,
                float* __restrict__ out) {
    extern __shared__ char smraw[];
    f16* h1s = (f16*)smraw;              // [32][LDH]
    f16* s1s = h1s + SB * LDH;           // [32][LDH]
    f16* h2s = s1s + SB * LDH;           // [32][LDH]
    f16* ys  = h2s + SB * LDH;           // [32][LDY]
    float* yt = (float*)(ys + SB * LDY); // [32][LDF]
    float* ks = yt + SB * LDF;           // [5][32][LDK]
    float* trs = ks + 5 * SB * LDK;
    float* lds = trs + SB;

    const int tid  = threadIdx.x;
    const int lane = tid & 31;
    const int w    = tid >> 5;
    const int qrow = lane >> 2;
    const int qcol = lane & 3;
    const int gbase = blockIdx.x * SB;

    const int lrow  = ((lane >> 4) << 3) + (lane & 7);
    const int lcol8 = ((lane >> 3) & 1) << 3;
    const uint32_t sa_h1 = (uint32_t)__cvta_generic_to_shared(h1s + lrow * LDH + lcol8);
    const uint32_t sa_s1 = (uint32_t)__cvta_generic_to_shared(s1s + lrow * LDH + lcol8);
    const uint32_t sa_h2 = (uint32_t)__cvta_generic_to_shared(h2s + lrow * LDH + lcol8);
    const uint32_t sa_ys = (uint32_t)__cvta_generic_to_shared(ys  + lrow * LDY + lcol8);

    // Hoisted fragment-stream base pointers (per warp, per matrix).
    const uint4* pW1h0 = (const uint4*)g_W1hf + (2 * w + 0) * 4 * 32 + lane;
    const uint4* pW1h1 = (const uint4*)g_W1hf + (2 * w + 1) * 4 * 32 + lane;
    const uint4* pW1l0 = (const uint4*)g_W1lf + (2 * w + 0) * 4 * 32 + lane;
    const uint4* pW1l1 = (const uint4*)g_W1lf + (2 * w + 1) * 4 * 32 + lane;
    const uint4* pW2h0 = (const uint4*)g_W2hf + (2 * w + 0) * 16 * 32 + lane;
    const uint4* pW2h1 = (const uint4*)g_W2hf + (2 * w + 1) * 16 * 32 + lane;
    const uint4* pW2l0 = (const uint4*)g_W2lf + (2 * w + 0) * 16 * 32 + lane;
    const uint4* pW2l1 = (const uint4*)g_W2lf + (2 * w + 1) * 16 * 32 + lane;
    const uint4* pEh0  = (const uint4*)g_Ehf  + (2 * w + 0) * 16 * 32 + lane;
    const uint4* pEh1  = (const uint4*)g_Ehf  + (2 * w + 1) * 16 * 32 + lane;
    const int mt = w & 3;
    const int np = w >> 2;
    const uint4* pW3h  = (const uint4*)g_W3hf + mt * 16 * 32 + lane;
    const uint4* pW3l  = (const uint4*)g_W3lf + mt * 16 * 32 + lane;

    const float dt = Tptr[0] * (1.0f / NSTEPS);

    {
        const int d = tid & 63;
        const int srow = tid >> 6;
        #pragma unroll
        for (int c = 0; c < 8; ++c) {
            int s = srow * 8 + c;
            float v = x[(gbase + s) * DB + d];
            yt[s * LDF + d] = v;
            ys[s * LDY + d] = __float2half(v);
        }
        if (tid < SB) { lds[tid] = ld0[gbase + tid]; trs[tid] = 0.f; }
    }

    for (int step = 0; step < NSTEPS; ++step) {
        for (int st = 0; st < 6; ++st) {
            __syncthreads();                    // (1) yst ready

            // ================= Phase A: z1 = W1 yst + b1 =================
            {
                float acc[2][4][4];
                #pragma unroll
                for (int m2 = 0; m2 < 2; ++m2)
                    #pragma unroll
                    for (int nt = 0; nt < 4; ++nt)
                        #pragma unroll
                        for (int e = 0; e < 4; ++e) acc[m2][nt][e] = 0.f;

                const uint4* ph0 = pW1h0; const uint4* ph1 = pW1h1;
                const uint4* pl0 = pW1l0; const uint4* pl1 = pW1l1;
                uint32_t ahb[2][2][4], alb[2][2][4], bhb[2][8];
                ldfp(ph0, ahb[0][0]); ldfp(ph1, ahb[0][1]);
                ldfp(pl0, alb[0][0]); ldfp(pl1, alb[0][1]);
                LDSM4(bhb[0][0], bhb[0][1], bhb[0][2], bhb[0][3], sa_ys);
                LDSM4(bhb[0][4], bhb[0][5], bhb[0][6], bhb[0][7], sa_ys + 16 * LDY * 2);
                #pragma unroll
                for (int kc = 0; kc < 4; ++kc) {
                    const int cur = kc & 1, nxt = cur ^ 1;
                    if (kc < 3) {
                        int koff = (kc + 1) * 32;
                        LDSM4(bhb[nxt][0], bhb[nxt][1], bhb[nxt][2], bhb[nxt][3], sa_ys + koff);
                        LDSM4(bhb[nxt][4], bhb[nxt][5], bhb[nxt][6], bhb[nxt][7],
                              sa_ys + 16 * LDY * 2 + koff);
                        ldfp(ph0 + 32, ahb[nxt][0]); ldfp(ph1 + 32, ahb[nxt][1]);
                        ldfp(pl0 + 32, alb[nxt][0]); ldfp(pl1 + 32, alb[nxt][1]);
                        ph0 += 32; ph1 += 32; pl0 += 32; pl1 += 32;
                    }
                    #pragma unroll
                    for (int m2 = 0; m2 < 2; ++m2)
                        #pragma unroll
                        for (int nt = 0; nt < 4; ++nt) {
                            uint32_t b0 = bhb[cur][(nt >> 1) * 4 + (nt & 1) * 2];
                            uint32_t b1 = bhb[cur][(nt >> 1) * 4 + (nt & 1) * 2 + 1];
                            MMA16816(acc[m2][nt], ahb[cur][m2][0], ahb[cur][m2][1],
                                     ahb[cur][m2][2], ahb[cur][m2][3], b0, b1);
                        }
                    #pragma unroll
                    for (int m2 = 0; m2 < 2; ++m2)
                        #pragma unroll
                        for (int nt = 0; nt < 4; ++nt) {
                            uint32_t b0 = bhb[cur][(nt >> 1) * 4 + (nt & 1) * 2];
                            uint32_t b1 = bhb[cur][(nt >> 1) * 4 + (nt & 1) * 2 + 1];
                            MMA16816(acc[m2][nt], alb[cur][m2][0], alb[cur][m2][1],
                                     alb[cur][m2][2], alb[cur][m2][3], b0, b1);
                        }
                }
                // epilogue A
                #pragma unroll
                for (int m2 = 0; m2 < 2; ++m2) {
                    int mrow = 16 * (2 * w + m2);
                    float bm0 = b1g[mrow + qrow], bm1 = b1g[mrow + qrow + 8];
                    #pragma unroll
                    for (int nt = 0; nt < 4; ++nt) {
                        #pragma unroll
                        for (int e = 0; e < 4; ++e) {
                            int m = mrow + qrow + ((e >> 1) << 3);
                            int n = nt * 8 + 2 * qcol + (e & 1);
                            float z = acc[m2][nt][e] + ((e >> 1) ? bm1 : bm0);
                            float sp, sg;
                            act(z, sp, sg);
                            h1s[n * LDH + m] = __float2half(sp);
                            s1s[n * LDH + m] = __float2half(sg);
                        }
                    }
                }
            }
            __syncthreads();                    // (2) h1/s1 ready

            // ===== Phase B: z2 = W2 h1 + b2 ; t = E s1 ; trace; h2 =======
            float accZ[2][4][4], accT[2][4][4];
            {
                #pragma unroll
                for (int m2 = 0; m2 < 2; ++m2)
                    #pragma unroll
                    for (int nt = 0; nt < 4; ++nt)
                        #pragma unroll
                        for (int e = 0; e < 4; ++e) accZ[m2][nt][e] = 0.f;

                // GEMM Z: (W2h + W2l) x h1, both streams depth-2 pipelined
                {
                    const uint4* ph0 = pW2h0; const uint4* ph1 = pW2h1;
                    const uint4* pl0 = pW2l0; const uint4* pl1 = pW2l1;
                    uint32_t ahb[2][2][4], alb[2][2][4], bhb[2][8];
                    ldfp(ph0, ahb[0][0]); ldfp(ph1, ahb[0][1]);
                    ldfp(pl0, alb[0][0]); ldfp(pl1, alb[0][1]);
                    LDSM4(bhb[0][0], bhb[0][1], bhb[0][2], bhb[0][3], sa_h1);
                    LDSM4(bhb[0][4], bhb[0][5], bhb[0][6], bhb[0][7], sa_h1 + 16 * LDH * 2);
                    #pragma unroll
                    for (int kc = 0; kc < 16; ++kc) {
                        const int cur = kc & 1, nxt = cur ^ 1;
                        if (kc < 15) {
                            int koff = (kc + 1) * 32;
                            LDSM4(bhb[nxt][0], bhb[nxt][1], bhb[nxt][2], bhb[nxt][3],
                                  sa_h1 + koff);
                            LDSM4(bhb[nxt][4], bhb[nxt][5], bhb[nxt][6], bhb[nxt][7],
                                  sa_h1 + 16 * LDH * 2 + koff);
                            ldfp(ph0 + 32, ahb[nxt][0]); ldfp(ph1 + 32, ahb[nxt][1]);
                            ldfp(pl0 + 32, alb[nxt][0]); ldfp(pl1 + 32, alb[nxt][1]);
                            ph0 += 32; ph1 += 32; pl0 += 32; pl1 += 32;
                        }
                        #pragma unroll
                        for (int m2 = 0; m2 < 2; ++m2)
                            #pragma unroll
                            for (int nt = 0; nt < 4; ++nt) {
                                uint32_t b0 = bhb[cur][(nt >> 1) * 4 + (nt & 1) * 2];
                                uint32_t b1 = bhb[cur][(nt >> 1) * 4 + (nt & 1) * 2 + 1];
                                MMA16816(accZ[m2][nt], ahb[cur][m2][0], ahb[cur][m2][1],
                                         ahb[cur][m2][2], ahb[cur][m2][3], b0, b1);
                            }
                        #pragma unroll
                        for (int m2 = 0; m2 < 2; ++m2)
                            #pragma unroll
                            for (int nt = 0; nt < 4; ++nt) {
                                uint32_t b0 = bhb[cur][(nt >> 1) * 4 + (nt & 1) * 2];
                                uint32_t b1 = bhb[cur][(nt >> 1) * 4 + (nt & 1) * 2 + 1];
                                MMA16816(accZ[m2][nt], alb[cur][m2][0], alb[cur][m2][1],
                                         alb[cur][m2][2], alb[cur][m2][3], b0, b1);
                            }
                    }
                }
                // GEMM T: Eh x s1 (single pass), both streams pipelined
                #pragma unroll
                for (int m2 = 0; m2 < 2; ++m2)
                    #pragma unroll
                    for (int nt = 0; nt < 4; ++nt)
                        #pragma unroll
                        for (int e = 0; e < 4; ++e) accT[m2][nt][e] = 0.f;
                {
                    const uint4* pe0 = pEh0; const uint4* pe1 = pEh1;
                    uint32_t ehb[2][2][4], bhb[2][8];
                    ldfp(pe0, ehb[0][0]); ldfp(pe1, ehb[0][1]);
                    LDSM4(bhb[0][0], bhb[0][1], bhb[0][2], bhb[0][3], sa_s1);
                    LDSM4(bhb[0][4], bhb[0][5], bhb[0][6], bhb[0][7], sa_s1 + 16 * LDH * 2);
                    #pragma unroll
                    for (int kc = 0; kc < 16; ++kc) {
                        const int cur = kc & 1, nxt = cur ^ 1;
                        if (kc < 15) {
                            int koff = (kc + 1) * 32;
                            LDSM4(bhb[nxt][0], bhb[nxt][1], bhb[nxt][2], bhb[nxt][3],
                                  sa_s1 + koff);
                            LDSM4(bhb[nxt][4], bhb[nxt][5], bhb[nxt][6], bhb[nxt][7],
                                  sa_s1 + 16 * LDH * 2 + koff);
                            ldfp(pe0 + 32, ehb[nxt][0]); ldfp(pe1 + 32, ehb[nxt][1]);
                            pe0 += 32; pe1 += 32;
                        }
                        #pragma unroll
                        for (int m2 = 0; m2 < 2; ++m2)
                            #pragma unroll
                            for (int nt = 0; nt < 4; ++nt) {
                                uint32_t b0 = bhb[cur][(nt >> 1) * 4 + (nt & 1) * 2];
                                uint32_t b1 = bhb[cur][(nt >> 1) * 4 + (nt & 1) * 2 + 1];
                                MMA16816(accT[m2][nt], ehb[cur][m2][0], ehb[cur][m2][1],
                                         ehb[cur][m2][2], ehb[cur][m2][3], b0, b1);
                            }
                    }
                }
            }
            // epilogue B (no barrier: writes fresh h2s + trs atomics only)
            {
                #pragma unroll
                for (int nt = 0; nt < 4; ++nt) {
                    float p0 = 0.f, p1 = 0.f;
                    #pragma unroll
                    for (int m2 = 0; m2 < 2; ++m2) {
                        int mrow = 16 * (2 * w + m2);
                        float bm0 = b2g[mrow + qrow], bm1 = b2g[mrow + qrow + 8];
                        #pragma unroll
                        for (int e = 0; e < 4; ++e) {
                            int m = mrow + qrow + ((e >> 1) << 3);
                            int n = nt * 8 + 2 * qcol + (e & 1);
                            float z = accZ[m2][nt][e] + ((e >> 1) ? bm1 : bm0);
                            float sp, sg;
                            act(z, sp, sg);
                            h2s[n * LDH + m] = __float2half(sp);
                            float contrib = sg * accT[m2][nt][e];
                            if (e & 1) p1 += contrib; else p0 += contrib;
                        }
                    }
                    #pragma unroll
                    for (int msk = 4; msk <= 16; msk <<= 1) {
                        p0 += __shfl_xor_sync(0xFFFFFFFFu, p0, msk);
                        p1 += __shfl_xor_sync(0xFFFFFFFFu, p1, msk);
                    }
                    if (qrow == 0) {
                        atomicAdd(&trs[nt * 8 + 2 * qcol], p0);
                        atomicAdd(&trs[nt * 8 + 2 * qcol + 1], p1);
                    }
                }
            }
            __syncthreads();                    // (3) h2s + trs ready

            if (tid < SB) {
                lds[tid] += dt * c_CL[st] * trs[tid];
                trs[tid] = 0.f;
            }

            // ===== Phase C: dy = W3 h2 + b3 ; k store; stage combine ======
            {
                const uint32_t sa_c = sa_h2 + np * 16 * LDH * 2;
                float acc[2][4];
                #pragma unroll
                for (int f = 0; f < 2; ++f)
                    #pragma unroll
                    for (int e = 0; e < 4; ++e) acc[f][e] = 0.f;

                const uint4* ph = pW3h; const uint4* pl = pW3l;
                uint32_t ahb[2][4], alb[2][4], bhb[2][4];
                ldfp(ph, ahb[0]); ldfp(pl, alb[0]);
                LDSM4(bhb[0][0], bhb[0][1], bhb[0][2], bhb[0][3], sa_c);
                #pragma unroll
                for (int kc = 0; kc < 16; ++kc) {
                    const int cur = kc & 1, nxt = cur ^ 1;
                    if (kc < 15) {
                        LDSM4(bhb[nxt][0], bhb[nxt][1], bhb[nxt][2], bhb[nxt][3],
                              sa_c + (kc + 1) * 32);
                        ldfp(ph + 32, ahb[nxt]); ldfp(pl + 32, alb[nxt]);
                        ph += 32; pl += 32;
                    }
                    MMA16816(acc[0], ahb[cur][0], ahb[cur][1], ahb[cur][2], ahb[cur][3],
                             bhb[cur][0], bhb[cur][1]);
                    MMA16816(acc[1], ahb[cur][0], ahb[cur][1], ahb[cur][2], ahb[cur][3],
                             bhb[cur][2], bhb[cur][3]);
                    MMA16816(acc[0], alb[cur][0], alb[cur][1], alb[cur][2], alb[cur][3],
                             bhb[cur][0], bhb[cur][1]);
                    MMA16816(acc[1], alb[cur][0], alb[cur][1], alb[cur][2], alb[cur][3],
                             bhb[cur][2], bhb[cur][3]);
                }
                // epilogue: bias, store k (SMEM), Dopri5 combine, write ys/yt
                float bm0 = b3g[16 * mt + qrow], bm1 = b3g[16 * mt + qrow + 8];
                float alast = c_A[st][st];
                #pragma unroll
                for (int f = 0; f < 2; ++f) {
                    #pragma unroll
                    for (int e = 0; e < 4; ++e) {
                        int dd = 16 * mt + qrow + ((e >> 1) << 3);
                        int s  = (2 * np + f) * 8 + 2 * qcol + (e & 1);
                        float v = acc[f][e] + ((e >> 1) ? bm1 : bm0);
                        if (st < 5) ks[(st * SB + s) * LDK + dd] = v;
                        float comb = alast * v;
                        for (int m = 0; m < st; ++m)
                            comb += c_A[st][m] * ks[(m * SB + s) * LDK + dd];
                        float nv = yt[s * LDF + dd] + dt * comb;
                        if (st == 5) yt[s * LDF + dd] = nv;
                        ys[s * LDY + dd] = __float2half(nv);
                    }
                }
            }
        } // stages
    } // steps

    __syncthreads();
    {
        const int d = tid & 63;
        const int srow = tid >> 6;
        #pragma unroll
        for (int c = 0; c < 8; ++c) {
            int s = srow * 8 + c;
            out[(gbase + s) * DB + d] = yt[s * LDF + d];
        }
        if (tid < SB) out[BT * DB + gbase + tid] = lds[tid];
    }
}

// ---------------------------------------------------------------------------
#define SMEM_BYTES ((3 * SB * LDH + SB * LDY) * 2 + \
                    (SB * LDF + 5 * SB * LDK + 2 * SB) * 4)

extern "C" void kernel_launch(void* const* d_in, const int* in_sizes, int n_in,
                              void* d_out, int out_size) {
    const float* x   = (const float*)d_in[0];
    const float* ld0 = (const float*)d_in[1];
    const float* W1  = (const float*)d_in[2];
    const float* b1  = (const float*)d_in[3];
    const float* W2  = (const float*)d_in[4];
    const float* b2  = (const float*)d_in[5];
    const float* W3  = (const float*)d_in[6];
    const float* b3  = (const float*)d_in[7];
    const float* T   = (const float*)d_in[8];
    float* out = (float*)d_out;

    cudaFuncSetAttribute(cnf_main_kernel,
                         cudaFuncAttributeMaxDynamicSharedMemorySize, SMEM_BYTES);

    cnf_prep_kernel<<<HB, HB>>>(W1, W2, W3);
    cnf_main_kernel<<<NBLOCKS, NTHREADS, SMEM_BYTES>>>(x, ld0, b1, b2, b3, T, out);
}

// round 17
// speedup vs baseline: 1.1887x; 1.1887x over previous
#include <cuda_runtime.h>
#include <cuda_fp16.h>
#include <cstdint>

// ---------------------------------------------------------------------------
// CNF Dopri5 solver, tensor-core GEMMs.
// R17 = R14 (best, 930us) with the W2-lo correction pass removed:
// W1, W3 remain fp16 2-pass; W2 and E are single-pass fp16.
// 32 samples/CTA, 256 CTAs, 256 threads, 2 CTAs/SM.
// ---------------------------------------------------------------------------

#define DB 64
#define HB 256
#define BT 8192
#define NSTEPS 10
#define SB 32
#define NTHREADS 256
#define NBLOCKS (BT / SB)      // 256

#define LDH 264
#define LDY 72
#define LDF 68
#define LDK 68

typedef __half f16;

__device__ __align__(16) f16 g_W1hf[HB * DB], g_W1lf[HB * DB];     // KC=4
__device__ __align__(16) f16 g_W2hf[HB * HB];                      // KC=16 single
__device__ __align__(16) f16 g_Ehf [HB * HB];                      // KC=16 single
__device__ __align__(16) f16 g_W3hf[DB * HB], g_W3lf[DB * HB];     // KC=16

__constant__ float c_A[6][6] = {
    { 0.2f, 0.f, 0.f, 0.f, 0.f, 0.f },
    { 3.f/40.f, 9.f/40.f, 0.f, 0.f, 0.f, 0.f },
    { 44.f/45.f, -56.f/15.f, 32.f/9.f, 0.f, 0.f, 0.f },
    { 19372.f/6561.f, -25360.f/2187.f, 64448.f/6561.f, -212.f/729.f, 0.f, 0.f },
    { 9017.f/3168.f, -355.f/33.f, 46732.f/5247.f, 49.f/176.f, -5103.f/18656.f, 0.f },
    { 35.f/384.f, 0.f, 500.f/1113.f, 125.f/192.f, -2187.f/6784.f, 11.f/84.f }
};
__constant__ float c_CL[6] = {
    35.f/384.f, 0.f, 500.f/1113.f, 125.f/192.f, -2187.f/6784.f, 11.f/84.f
};

__device__ __forceinline__ void wsplit(float v, f16& hi, f16& lo) {
    hi = __float2half(v);
    lo = __float2half(v - __half2float(hi));
}

__device__ __forceinline__ int pidx(int m, int k, int KC) {
    int mtile = m >> 4;
    int kc    = k >> 4;
    int lane  = (m & 7) * 4 + ((k & 7) >> 1);
    int reg   = ((k >> 3) & 1) * 2 + ((m >> 3) & 1);
    int half_ = k & 1;
    return (((mtile * KC + kc) * 32 + lane) * 4 + reg) * 2 + half_;
}

// 2-MUFU activation: softplus + sigmoid from tanh.approx + log.
__device__ __forceinline__ void act(float z, float& sp, float& sg) {
    float u;
    asm("tanh.approx.f32 %0, %1;" : "=f"(u) : "f"(-0.5f * fabsf(z)));
    float q = 0.5f - 0.5f * u;             // sigmoid(|z|) in [0.5, 1)
    sp = fmaxf(z, 0.f) - __logf(q);        // softplus(z)
    sg = (z > 0.f) ? q : 1.f - q;          // sigmoid(z)
}

#define MMA16816(dd, a0, a1, a2, a3, bb0, bb1) \
    asm volatile("mma.sync.aligned.m16n8k16.row.col.f32.f16.f16.f32 " \
        "{%0,%1,%2,%3}, {%4,%5,%6,%7}, {%8,%9}, {%0,%1,%2,%3};" \
        : "+f"(dd[0]), "+f"(dd[1]), "+f"(dd[2]), "+f"(dd[3]) \
        : "r"(a0), "r"(a1), "r"(a2), "r"(a3), "r"(bb0), "r"(bb1))

#define LDSM4(rr0, rr1, rr2, rr3, saddr) \
    asm volatile("ldmatrix.sync.aligned.m8n8.x4.shared.b16 {%0,%1,%2,%3}, [%4];" \
        : "=r"(rr0), "=r"(rr1), "=r"(rr2), "=r"(rr3) : "r"(saddr))

// Fragment load from a hoisted pointer (strength-reduced addressing).
__device__ __forceinline__ void ldfp(const uint4* p, uint32_t a[4]) {
    uint4 v = *p;
    a[0] = v.x; a[1] = v.y; a[2] = v.z; a[3] = v.w;
}

// ---------------------------------------------------------------------------
__global__ void cnf_prep_kernel(const float* __restrict__ W1,
                                const float* __restrict__ W2,
                                const float* __restrict__ W3) {
    int i = blockIdx.x;
    int j = threadIdx.x;
    float g = 0.f;
    #pragma unroll
    for (int d = 0; d < DB; ++d)
        g += W1[i * DB + d] * W3[d * HB + j];
    g_Ehf[pidx(j, i, 16)] = __float2half(W2[j * HB + i] * g);
    g_W2hf[pidx(i, j, 16)] = __float2half(W2[i * HB + j]);
    if (j < DB) {
        int q = pidx(i, j, 4);
        wsplit(W1[i * DB + j], g_W1hf[q], g_W1lf[q]);
    }
    if (i < DB) {
        int q = pidx(i, j, 16);
        wsplit(W3[i * HB + j], g_W3hf[q], g_W3lf[q]);
    }
}

// ---------------------------------------------------------------------------
__global__ void __launch_bounds__(NTHREADS, 2)
cnf_main_kernel(const float* __restrict__ x,
                const float* __restrict__ ld0,
                const float* __restrict__ b1g,
                const float* __restrict__ b2g,
                const float* __restrict__ b3g,
                const float* __restrict__ Tptr,
                float* __restrict__ out) {
    extern __shared__ char smraw[];
    f16* h1s = (f16*)smraw;              // [32][LDH]
    f16* s1s = h1s + SB * LDH;           // [32][LDH]
    f16* h2s = s1s + SB * LDH;           // [32][LDH]
    f16* ys  = h2s + SB * LDH;           // [32][LDY]
    float* yt = (float*)(ys + SB * LDY); // [32][LDF]
    float* ks = yt + SB * LDF;           // [5][32][LDK]
    float* trs = ks + 5 * SB * LDK;
    float* lds = trs + SB;

    const int tid  = threadIdx.x;
    const int lane = tid & 31;
    const int w    = tid >> 5;
    const int qrow = lane >> 2;
    const int qcol = lane & 3;
    const int gbase = blockIdx.x * SB;

    const int lrow  = ((lane >> 4) << 3) + (lane & 7);
    const int lcol8 = ((lane >> 3) & 1) << 3;
    const uint32_t sa_h1 = (uint32_t)__cvta_generic_to_shared(h1s + lrow * LDH + lcol8);
    const uint32_t sa_s1 = (uint32_t)__cvta_generic_to_shared(s1s + lrow * LDH + lcol8);
    const uint32_t sa_h2 = (uint32_t)__cvta_generic_to_shared(h2s + lrow * LDH + lcol8);
    const uint32_t sa_ys = (uint32_t)__cvta_generic_to_shared(ys  + lrow * LDY + lcol8);

    // Hoisted fragment-stream base pointers (per warp, per matrix).
    const uint4* pW1h0 = (const uint4*)g_W1hf + (2 * w + 0) * 4 * 32 + lane;
    const uint4* pW1h1 = (const uint4*)g_W1hf + (2 * w + 1) * 4 * 32 + lane;
    const uint4* pW1l0 = (const uint4*)g_W1lf + (2 * w + 0) * 4 * 32 + lane;
    const uint4* pW1l1 = (const uint4*)g_W1lf + (2 * w + 1) * 4 * 32 + lane;
    const uint4* pW2h0 = (const uint4*)g_W2hf + (2 * w + 0) * 16 * 32 + lane;
    const uint4* pW2h1 = (const uint4*)g_W2hf + (2 * w + 1) * 16 * 32 + lane;
    const uint4* pEh0  = (const uint4*)g_Ehf  + (2 * w + 0) * 16 * 32 + lane;
    const uint4* pEh1  = (const uint4*)g_Ehf  + (2 * w + 1) * 16 * 32 + lane;
    const int mt = w & 3;
    const int np = w >> 2;
    const uint4* pW3h  = (const uint4*)g_W3hf + mt * 16 * 32 + lane;
    const uint4* pW3l  = (const uint4*)g_W3lf + mt * 16 * 32 + lane;

    const float dt = Tptr[0] * (1.0f / NSTEPS);

    {
        const int d = tid & 63;
        const int srow = tid >> 6;
        #pragma unroll
        for (int c = 0; c < 8; ++c) {
            int s = srow * 8 + c;
            float v = x[(gbase + s) * DB + d];
            yt[s * LDF + d] = v;
            ys[s * LDY + d] = __float2half(v);
        }
        if (tid < SB) { lds[tid] = ld0[gbase + tid]; trs[tid] = 0.f; }
    }

    for (int step = 0; step < NSTEPS; ++step) {
        for (int st = 0; st < 6; ++st) {
            __syncthreads();                    // (1) yst ready

            // ================= Phase A: z1 = W1 yst + b1 =================
            {
                float acc[2][4][4];
                #pragma unroll
                for (int m2 = 0; m2 < 2; ++m2)
                    #pragma unroll
                    for (int nt = 0; nt < 4; ++nt)
                        #pragma unroll
                        for (int e = 0; e < 4; ++e) acc[m2][nt][e] = 0.f;

                const uint4* ph0 = pW1h0; const uint4* ph1 = pW1h1;
                const uint4* pl0 = pW1l0; const uint4* pl1 = pW1l1;
                uint32_t ahb[2][2][4], alb[2][2][4];
                ldfp(ph0, ahb[0][0]); ldfp(ph1, ahb[0][1]);
                ldfp(pl0, alb[0][0]); ldfp(pl1, alb[0][1]);
                #pragma unroll
                for (int kc = 0; kc < 4; ++kc) {
                    const int cur = kc & 1, nxt = cur ^ 1;
                    if (kc < 3) {
                        ldfp(ph0 + 32, ahb[nxt][0]); ldfp(ph1 + 32, ahb[nxt][1]);
                        ldfp(pl0 + 32, alb[nxt][0]); ldfp(pl1 + 32, alb[nxt][1]);
                        ph0 += 32; ph1 += 32; pl0 += 32; pl1 += 32;
                    }
                    int koff = kc * 32;
                    uint32_t bh[8];
                    LDSM4(bh[0], bh[1], bh[2], bh[3], sa_ys + koff);
                    LDSM4(bh[4], bh[5], bh[6], bh[7], sa_ys + 16 * LDY * 2 + koff);
                    #pragma unroll
                    for (int m2 = 0; m2 < 2; ++m2)
                        #pragma unroll
                        for (int nt = 0; nt < 4; ++nt) {
                            uint32_t b0 = bh[(nt >> 1) * 4 + (nt & 1) * 2];
                            uint32_t b1 = bh[(nt >> 1) * 4 + (nt & 1) * 2 + 1];
                            MMA16816(acc[m2][nt], ahb[cur][m2][0], ahb[cur][m2][1],
                                     ahb[cur][m2][2], ahb[cur][m2][3], b0, b1);
                        }
                    #pragma unroll
                    for (int m2 = 0; m2 < 2; ++m2)
                        #pragma unroll
                        for (int nt = 0; nt < 4; ++nt) {
                            uint32_t b0 = bh[(nt >> 1) * 4 + (nt & 1) * 2];
                            uint32_t b1 = bh[(nt >> 1) * 4 + (nt & 1) * 2 + 1];
                            MMA16816(acc[m2][nt], alb[cur][m2][0], alb[cur][m2][1],
                                     alb[cur][m2][2], alb[cur][m2][3], b0, b1);
                        }
                }
                // epilogue A
                #pragma unroll
                for (int m2 = 0; m2 < 2; ++m2) {
                    int mrow = 16 * (2 * w + m2);
                    float bm0 = b1g[mrow + qrow], bm1 = b1g[mrow + qrow + 8];
                    #pragma unroll
                    for (int nt = 0; nt < 4; ++nt) {
                        #pragma unroll
                        for (int e = 0; e < 4; ++e) {
                            int m = mrow + qrow + ((e >> 1) << 3);
                            int n = nt * 8 + 2 * qcol + (e & 1);
                            float z = acc[m2][nt][e] + ((e >> 1) ? bm1 : bm0);
                            float sp, sg;
                            act(z, sp, sg);
                            h1s[n * LDH + m] = __float2half(sp);
                            s1s[n * LDH + m] = __float2half(sg);
                        }
                    }
                }
            }
            __syncthreads();                    // (2) h1/s1 ready

            // ===== Phase B: z2 = W2 h1 + b2 ; t = E s1 ; trace; h2 =======
            float accZ[2][4][4], accT[2][4][4];
            {
                #pragma unroll
                for (int m2 = 0; m2 < 2; ++m2)
                    #pragma unroll
                    for (int nt = 0; nt < 4; ++nt)
                        #pragma unroll
                        for (int e = 0; e < 4; ++e) accZ[m2][nt][e] = 0.f;

                // GEMM Z: W2h x h1 (single pass), double-buffered frags
                {
                    const uint4* ph0 = pW2h0; const uint4* ph1 = pW2h1;
                    uint32_t ahb[2][2][4];
                    ldfp(ph0, ahb[0][0]); ldfp(ph1, ahb[0][1]);
                    #pragma unroll
                    for (int kc = 0; kc < 16; ++kc) {
                        const int cur = kc & 1, nxt = cur ^ 1;
                        if (kc < 15) {
                            ldfp(ph0 + 32, ahb[nxt][0]); ldfp(ph1 + 32, ahb[nxt][1]);
                            ph0 += 32; ph1 += 32;
                        }
                        int koff = kc * 32;
                        uint32_t bh[8];
                        LDSM4(bh[0], bh[1], bh[2], bh[3], sa_h1 + koff);
                        LDSM4(bh[4], bh[5], bh[6], bh[7], sa_h1 + 16 * LDH * 2 + koff);
                        #pragma unroll
                        for (int m2 = 0; m2 < 2; ++m2)
                            #pragma unroll
                            for (int nt = 0; nt < 4; ++nt) {
                                uint32_t b0 = bh[(nt >> 1) * 4 + (nt & 1) * 2];
                                uint32_t b1 = bh[(nt >> 1) * 4 + (nt & 1) * 2 + 1];
                                MMA16816(accZ[m2][nt], ahb[cur][m2][0], ahb[cur][m2][1],
                                         ahb[cur][m2][2], ahb[cur][m2][3], b0, b1);
                            }
                    }
                }
                // GEMM T: Eh x s1 (single pass), double-buffered
                #pragma unroll
                for (int m2 = 0; m2 < 2; ++m2)
                    #pragma unroll
                    for (int nt = 0; nt < 4; ++nt)
                        #pragma unroll
                        for (int e = 0; e < 4; ++e) accT[m2][nt][e] = 0.f;
                {
                    const uint4* pe0 = pEh0; const uint4* pe1 = pEh1;
                    uint32_t ehb[2][2][4];
                    ldfp(pe0, ehb[0][0]); ldfp(pe1, ehb[0][1]);
                    #pragma unroll
                    for (int kc = 0; kc < 16; ++kc) {
                        const int cur = kc & 1, nxt = cur ^ 1;
                        if (kc < 15) {
                            ldfp(pe0 + 32, ehb[nxt][0]); ldfp(pe1 + 32, ehb[nxt][1]);
                            pe0 += 32; pe1 += 32;
                        }
                        int koff = kc * 32;
                        uint32_t bh[8];
                        LDSM4(bh[0], bh[1], bh[2], bh[3], sa_s1 + koff);
                        LDSM4(bh[4], bh[5], bh[6], bh[7], sa_s1 + 16 * LDH * 2 + koff);
                        #pragma unroll
                        for (int m2 = 0; m2 < 2; ++m2)
                            #pragma unroll
                            for (int nt = 0; nt < 4; ++nt) {
                                uint32_t b0 = bh[(nt >> 1) * 4 + (nt & 1) * 2];
                                uint32_t b1 = bh[(nt >> 1) * 4 + (nt & 1) * 2 + 1];
                                MMA16816(accT[m2][nt], ehb[cur][m2][0], ehb[cur][m2][1],
                                         ehb[cur][m2][2], ehb[cur][m2][3], b0, b1);
                            }
                    }
                }
            }
            // epilogue B (no barrier: writes fresh h2s + trs atomics only)
            {
                #pragma unroll
                for (int nt = 0; nt < 4; ++nt) {
                    float p0 = 0.f, p1 = 0.f;
                    #pragma unroll
                    for (int m2 = 0; m2 < 2; ++m2) {
                        int mrow = 16 * (2 * w + m2);
                        float bm0 = b2g[mrow + qrow], bm1 = b2g[mrow + qrow + 8];
                        #pragma unroll
                        for (int e = 0; e < 4; ++e) {
                            int m = mrow + qrow + ((e >> 1) << 3);
                            int n = nt * 8 + 2 * qcol + (e & 1);
                            float z = accZ[m2][nt][e] + ((e >> 1) ? bm1 : bm0);
                            float sp, sg;
                            act(z, sp, sg);
                            h2s[n * LDH + m] = __float2half(sp);
                            float contrib = sg * accT[m2][nt][e];
                            if (e & 1) p1 += contrib; else p0 += contrib;
                        }
                    }
                    #pragma unroll
                    for (int msk = 4; msk <= 16; msk <<= 1) {
                        p0 += __shfl_xor_sync(0xFFFFFFFFu, p0, msk);
                        p1 += __shfl_xor_sync(0xFFFFFFFFu, p1, msk);
                    }
                    if (qrow == 0) {
                        atomicAdd(&trs[nt * 8 + 2 * qcol], p0);
                        atomicAdd(&trs[nt * 8 + 2 * qcol + 1], p1);
                    }
                }
            }
            __syncthreads();                    // (3) h2s + trs ready

            if (tid < SB) {
                lds[tid] += dt * c_CL[st] * trs[tid];
                trs[tid] = 0.f;
            }

            // ===== Phase C: dy = W3 h2 + b3 ; k store; stage combine ======
            {
                const uint32_t sa_c = sa_h2 + np * 16 * LDH * 2;
                float acc[2][4];
                #pragma unroll
                for (int f = 0; f < 2; ++f)
                    #pragma unroll
                    for (int e = 0; e < 4; ++e) acc[f][e] = 0.f;

                const uint4* ph = pW3h; const uint4* pl = pW3l;
                uint32_t ahb[2][4], alb[2][4];
                ldfp(ph, ahb[0]); ldfp(pl, alb[0]);
                #pragma unroll
                for (int kc = 0; kc < 16; ++kc) {
                    const int cur = kc & 1, nxt = cur ^ 1;
                    if (kc < 15) {
                        ldfp(ph + 32, ahb[nxt]); ldfp(pl + 32, alb[nxt]);
                        ph += 32; pl += 32;
                    }
                    int koff = kc * 32;
                    uint32_t bh[4];
                    LDSM4(bh[0], bh[1], bh[2], bh[3], sa_c + koff);
                    MMA16816(acc[0], ahb[cur][0], ahb[cur][1], ahb[cur][2], ahb[cur][3], bh[0], bh[1]);
                    MMA16816(acc[1], ahb[cur][0], ahb[cur][1], ahb[cur][2], ahb[cur][3], bh[2], bh[3]);
                    MMA16816(acc[0], alb[cur][0], alb[cur][1], alb[cur][2], alb[cur][3], bh[0], bh[1]);
                    MMA16816(acc[1], alb[cur][0], alb[cur][1], alb[cur][2], alb[cur][3], bh[2], bh[3]);
                }
                // epilogue: bias, store k (SMEM), Dopri5 combine, write ys/yt
                float bm0 = b3g[16 * mt + qrow], bm1 = b3g[16 * mt + qrow + 8];
                float alast = c_A[st][st];
                #pragma unroll
                for (int f = 0; f < 2; ++f) {
                    #pragma unroll
                    for (int e = 0; e < 4; ++e) {
                        int dd = 16 * mt + qrow + ((e >> 1) << 3);
                        int s  = (2 * np + f) * 8 + 2 * qcol + (e & 1);
                        float v = acc[f][e] + ((e >> 1) ? bm1 : bm0);
                        if (st < 5) ks[(st * SB + s) * LDK + dd] = v;
                        float comb = alast * v;
                        for (int m = 0; m < st; ++m)
                            comb += c_A[st][m] * ks[(m * SB + s) * LDK + dd];
                        float nv = yt[s * LDF + dd] + dt * comb;
                        if (st == 5) yt[s * LDF + dd] = nv;
                        ys[s * LDY + dd] = __float2half(nv);
                    }
                }
            }
        } // stages
    } // steps

    __syncthreads();
    {
        const int d = tid & 63;
        const int srow = tid >> 6;
        #pragma unroll
        for (int c = 0; c < 8; ++c) {
            int s = srow * 8 + c;
            out[(gbase + s) * DB + d] = yt[s * LDF + d];
        }
        if (tid < SB) out[BT * DB + gbase + tid] = lds[tid];
    }
}

// ---------------------------------------------------------------------------
#define SMEM_BYTES ((3 * SB * LDH + SB * LDY) * 2 + \
                    (SB * LDF + 5 * SB * LDK + 2 * SB) * 4)

extern "C" void kernel_launch(void* const* d_in, const int* in_sizes, int n_in,
                              void* d_out, int out_size) {
    const float* x   = (const float*)d_in[0];
    const float* ld0 = (const float*)d_in[1];
    const float* W1  = (const float*)d_in[2];
    const float* b1  = (const float*)d_in[3];
    const float* W2  = (const float*)d_in[4];
    const float* b2  = (const float*)d_in[5];
    const float* W3  = (const float*)d_in[6];
    const float* b3  = (const float*)d_in[7];
    const float* T   = (const float*)d_in[8];
    float* out = (float*)d_out;

    cudaFuncSetAttribute(cnf_main_kernel,
                         cudaFuncAttributeMaxDynamicSharedMemorySize, SMEM_BYTES);

    cnf_prep_kernel<<<HB, HB>>>(W1, W2, W3);
    cnf_main_kernel<<<NBLOCKS, NTHREADS, SMEM_BYTES>>>(x, ld0, b1, b2, b3, T, out);
}